// round 2
// baseline (speedup 1.0000x reference)
#include <cuda_runtime.h>
#include <cuda_bf16.h>
#include <math.h>

// Problem dims
#define BB 4
#define NN 1024
#define LL 1024
#define CC 1024
#define HH 16
#define DD 64
#define BH (BB*HH)          // 64
#define SCALE 0.125f        // D^-0.5
#define NEGV (-65504.0f)

// ---------------- scratch (device globals; no allocations allowed) ----------
__device__ float g_Q[BB*HH*NN*DD];   // (B,H,N,D) 16MB
__device__ float g_K[BB*HH*LL*DD];   // (B,H,L,D) 16MB
__device__ float g_V[BB*HH*LL*DD];   // (B,H,L,D) 16MB
__device__ float g_O[BB*NN*CC];      // (B,N,C)   16MB
__device__ int   g_maskflag;         // 1 => mask stored as 1-byte elems, 0 => 4-byte

// ---------------- mask element-width detection ------------------------------
// For 4-byte storage of 0/1 (int32 or float 0.0/1.0), the byte at offset
// (4k+1) is always 0. For 1-byte bool storage with ~10% ones, it is nonzero
// ~10% of the time. Scan 16384 such positions (64KB, safely < min buffer).
__global__ void detect_mask_kernel(const unsigned char* __restrict__ m) {
    __shared__ int s;
    if (threadIdx.x == 0) s = 0;
    __syncthreads();
    int found = 0;
    for (int j = threadIdx.x; j < 16384; j += 256)
        if (m[4*j + 1]) found = 1;
    if (found) atomicOr(&s, 1);
    __syncthreads();
    if (threadIdx.x == 0) g_maskflag = s;
}

// ---------------- generic NT GEMM: C[m,n] = sum_k A[m,k]*B[n,k] -------------
// 128x128 tile, BK=16, 256 threads, 8x8 microtile. Epilogue via functor.
struct EpiQ {
    __device__ void operator()(int m, int n, float v) const {
        int b = m >> 10, nr = m & 1023, h = n >> 6, d = n & 63;
        g_Q[(((b << 4) + h) * NN + nr) * DD + d] = v;
    }
};
struct EpiKV {
    __device__ void operator()(int m, int n, float v) const {
        int b = m >> 10, lr = m & 1023;
        if (n < CC) {
            int h = n >> 6, d = n & 63;
            g_K[(((b << 4) + h) * LL + lr) * DD + d] = v;
        } else {
            int c = n - CC, h = c >> 6, d = c & 63;
            g_V[(((b << 4) + h) * LL + lr) * DD + d] = v;
        }
    }
};
struct EpiProj {
    float* out; const float* pb;
    __device__ void operator()(int m, int n, float v) const {
        out[(long)m * CC + n] = v + pb[n];
    }
};

template <class Epi>
__global__ void __launch_bounds__(256)
gemm_nt_kernel(const float* __restrict__ A, const float* __restrict__ Bm,
               int K, Epi epi) {
    __shared__ float As[16][128];
    __shared__ float Bs[16][128];
    const float* Aeff = A ? A : g_O;   // proj GEMM reads scratch O

    int tid = threadIdx.x;
    int tx = tid & 15, ty = tid >> 4;
    int m0 = blockIdx.y * 128, n0 = blockIdx.x * 128;
    int lrow = tid >> 2, lq = tid & 3;

    float acc[8][8];
#pragma unroll
    for (int i = 0; i < 8; i++)
#pragma unroll
        for (int j = 0; j < 8; j++) acc[i][j] = 0.f;

    for (int k0 = 0; k0 < K; k0 += 16) {
#pragma unroll
        for (int r = 0; r < 2; r++) {
            int rr = lrow + r * 64;
            float4 va = *(const float4*)&Aeff[(long)(m0 + rr) * K + k0 + lq * 4];
            As[lq*4+0][rr] = va.x; As[lq*4+1][rr] = va.y;
            As[lq*4+2][rr] = va.z; As[lq*4+3][rr] = va.w;
            float4 vb = *(const float4*)&Bm[(long)(n0 + rr) * K + k0 + lq * 4];
            Bs[lq*4+0][rr] = vb.x; Bs[lq*4+1][rr] = vb.y;
            Bs[lq*4+2][rr] = vb.z; Bs[lq*4+3][rr] = vb.w;
        }
        __syncthreads();
#pragma unroll
        for (int kk = 0; kk < 16; kk++) {
            float ra[8], rb[8];
            *(float4*)&ra[0] = *(float4*)&As[kk][ty * 8];
            *(float4*)&ra[4] = *(float4*)&As[kk][ty * 8 + 4];
            *(float4*)&rb[0] = *(float4*)&Bs[kk][tx * 8];
            *(float4*)&rb[4] = *(float4*)&Bs[kk][tx * 8 + 4];
#pragma unroll
            for (int i = 0; i < 8; i++)
#pragma unroll
                for (int j = 0; j < 8; j++) acc[i][j] += ra[i] * rb[j];
        }
        __syncthreads();
    }
#pragma unroll
    for (int i = 0; i < 8; i++)
#pragma unroll
        for (int j = 0; j < 8; j++)
            epi(m0 + ty * 8 + i, n0 + tx * 8 + j, acc[i][j]);
}

// ---------------- S = scale*Q K^T, + mask + bias, write attn_wo_softmax ----
__global__ void __launch_bounds__(256)
attn_score_kernel(const float* __restrict__ bias,
                  const unsigned char* __restrict__ mask8,
                  float* __restrict__ attn) {
    __shared__ float As[16][128];
    __shared__ float Bs[16][128];
    int bh = blockIdx.z;
    const float* A  = g_Q + (long)bh * NN * DD;
    const float* Bm = g_K + (long)bh * LL * DD;

    int tid = threadIdx.x;
    int tx = tid & 15, ty = tid >> 4;
    int m0 = blockIdx.y * 128, n0 = blockIdx.x * 128;
    int lrow = tid >> 2, lq = tid & 3;

    float acc[8][8];
#pragma unroll
    for (int i = 0; i < 8; i++)
#pragma unroll
        for (int j = 0; j < 8; j++) acc[i][j] = 0.f;

    for (int k0 = 0; k0 < DD; k0 += 16) {
#pragma unroll
        for (int r = 0; r < 2; r++) {
            int rr = lrow + r * 64;
            float4 va = *(const float4*)&A[(long)(m0 + rr) * DD + k0 + lq * 4];
            As[lq*4+0][rr] = va.x; As[lq*4+1][rr] = va.y;
            As[lq*4+2][rr] = va.z; As[lq*4+3][rr] = va.w;
            float4 vb = *(const float4*)&Bm[(long)(n0 + rr) * DD + k0 + lq * 4];
            Bs[lq*4+0][rr] = vb.x; Bs[lq*4+1][rr] = vb.y;
            Bs[lq*4+2][rr] = vb.z; Bs[lq*4+3][rr] = vb.w;
        }
        __syncthreads();
#pragma unroll
        for (int kk = 0; kk < 16; kk++) {
            float ra[8], rb[8];
            *(float4*)&ra[0] = *(float4*)&As[kk][ty * 8];
            *(float4*)&ra[4] = *(float4*)&As[kk][ty * 8 + 4];
            *(float4*)&rb[0] = *(float4*)&Bs[kk][tx * 8];
            *(float4*)&rb[4] = *(float4*)&Bs[kk][tx * 8 + 4];
#pragma unroll
            for (int i = 0; i < 8; i++)
#pragma unroll
                for (int j = 0; j < 8; j++) acc[i][j] += ra[i] * rb[j];
        }
        __syncthreads();
    }

    int flag = g_maskflag;
    const unsigned int* mask32 = (const unsigned int*)mask8;
    int b = bh >> 4;
#pragma unroll
    for (int i = 0; i < 8; i++) {
        int m = m0 + ty * 8 + i;
        long rowb = ((long)bh * NN + m) * LL;
        long rowm = ((long)b  * NN + m) * LL;
#pragma unroll
        for (int j = 0; j < 8; j++) {
            int n = n0 + tx * 8 + j;
            bool msk = flag ? (mask8[rowm + n] != 0) : (mask32[rowm + n] != 0u);
            float v = msk ? NEGV : acc[i][j] * SCALE;
            attn[rowb + n] = v + bias[rowb + n];
        }
    }
}

// ---------------- fused softmax (over L) + P@V, writes O in (B,N,C) --------
__global__ void __launch_bounds__(256)
softmax_pv_kernel(const float* __restrict__ attn) {
    __shared__ float Ps[64][65];
    __shared__ float Vs[64][64];
    __shared__ float rmax[64], rinv[64];

    int bh = blockIdx.y;
    int r0 = blockIdx.x * 64;
    const float* S = attn + ((long)bh * NN + r0) * LL;

    int tid = threadIdx.x;
    int lane = tid & 31, warp = tid >> 5;

    // phase 1: per-row (max, sum) via online softmax, 8 warps x 8 rows
    for (int rr = 0; rr < 8; rr++) {
        int r = warp * 8 + rr;
        const float* srow = S + (long)r * LL;
        float m = -3.4e38f, s = 0.f;
        for (int i = lane; i < LL; i += 32) {
            float x = srow[i];
            float nm = fmaxf(m, x);
            s = s * __expf(m - nm) + __expf(x - nm);
            m = nm;
        }
#pragma unroll
        for (int off = 16; off; off >>= 1) {
            float om = __shfl_down_sync(0xffffffffu, m, off);
            float os = __shfl_down_sync(0xffffffffu, s, off);
            float nm = fmaxf(m, om);
            s = s * __expf(m - nm) + os * __expf(om - nm);
            m = nm;
        }
        if (lane == 0) { rmax[r] = m; rinv[r] = 1.0f / s; }
    }
    __syncthreads();

    // phase 2: O(64x64) = P(64x1024) @ V(1024x64), chunked by 64
    float acc[4][4];
#pragma unroll
    for (int i = 0; i < 4; i++)
#pragma unroll
        for (int j = 0; j < 4; j++) acc[i][j] = 0.f;

    int tx = tid & 15, ty = tid >> 4;
    for (int lc = 0; lc < LL; lc += 64) {
#pragma unroll
        for (int i = 0; i < 16; i++) {
            int idx = tid + 256 * i;
            int r = idx >> 6, l = idx & 63;
            float x = S[(long)r * LL + lc + l];
            Ps[r][l] = __expf(x - rmax[r]) * rinv[r];
        }
        const float* Vp = g_V + ((long)bh * LL + lc) * DD;
#pragma unroll
        for (int i = 0; i < 4; i++) {
            int idx = tid + 256 * i;
            int vr = idx >> 4, vq = idx & 15;
            *(float4*)&Vs[vr][vq * 4] = *(const float4*)&Vp[(long)vr * DD + vq * 4];
        }
        __syncthreads();
#pragma unroll
        for (int kk = 0; kk < 64; kk++) {
            float4 bv = *(float4*)&Vs[kk][tx * 4];
            float bb[4] = {bv.x, bv.y, bv.z, bv.w};
            float a[4];
#pragma unroll
            for (int i = 0; i < 4; i++) a[i] = Ps[ty * 4 + i][kk];
#pragma unroll
            for (int i = 0; i < 4; i++)
#pragma unroll
                for (int j = 0; j < 4; j++) acc[i][j] += a[i] * bb[j];
        }
        __syncthreads();
    }

    int b = bh >> 4, h = bh & 15;
#pragma unroll
    for (int i = 0; i < 4; i++) {
        int r = r0 + ty * 4 + i;
        float4 v = make_float4(acc[i][0], acc[i][1], acc[i][2], acc[i][3]);
        *(float4*)&g_O[((long)b * NN + r) * CC + h * DD + tx * 4] = v;
    }
}

// ---------------- launch --------------------------------------------------
extern "C" void kernel_launch(void* const* d_in, const int* in_sizes, int n_in,
                              void* d_out, int out_size) {
    const float* query  = (const float*)d_in[0];
    const float* memory = (const float*)d_in[1];
    const float* bias   = (const float*)d_in[2];
    const unsigned char* mask = (const unsigned char*)d_in[3];
    const float* q_w    = (const float*)d_in[4];
    const float* kv_w   = (const float*)d_in[5];
    const float* proj_w = (const float*)d_in[6];
    const float* proj_b = (const float*)d_in[7];

    float* x_out    = (float*)d_out;
    float* attn_out = x_out + (long)BB * NN * CC;   // x first, then attn_wo_softmax

    (void)in_sizes; (void)n_in; (void)out_size;

    detect_mask_kernel<<<1, 256>>>(mask);

    // Q = query @ q_w^T  -> g_Q (B,H,N,D)
    gemm_nt_kernel<<<dim3(CC / 128, (BB * NN) / 128), 256>>>(query, q_w, CC, EpiQ{});
    // KV = memory @ kv_w^T -> g_K, g_V (B,H,L,D)
    gemm_nt_kernel<<<dim3((2 * CC) / 128, (BB * LL) / 128), 256>>>(memory, kv_w, CC, EpiKV{});
    // S + mask + bias -> attn_wo_softmax (also softmax input)
    attn_score_kernel<<<dim3(LL / 128, NN / 128, BH), 256>>>(bias, mask, attn_out);
    // softmax + P@V -> g_O (B,N,C)
    softmax_pv_kernel<<<dim3(NN / 64, BH), 256>>>(attn_out);
    // x = O @ proj_w^T + b  (A=nullptr => read g_O)
    gemm_nt_kernel<<<dim3(CC / 128, (BB * NN) / 128), 256>>>(nullptr, proj_w, CC,
                                                             EpiProj{x_out, proj_b});
}